// round 9
// baseline (speedup 1.0000x reference)
#include <cuda_runtime.h>
#include <math.h>
#include <stdint.h>

#define T_DIM 8192
#define OBS 512
#define HID 2048
#define NOBJ 8

#define NCHUNK 128
#define LC (T_DIM / NCHUNK)   // 64

// ---------------------------------------------------------------------------
// Scratch (device globals; no allocation allowed).
// g_buf[0]=x_state (later y), g_buf[1]=B (later bx), g_buf[2]=C, g_buf[3]=delta_raw (later a)
__device__ float g_buf[4][(size_t)T_DIM * HID];
__device__ float g_aggA[NCHUNK * HID];
__device__ float g_aggB[NCHUNK * HID];
__device__ float g_hinit[NCHUNK * HID];
// int8 hi/lo (int16 emulation) operands + per-row scales
__device__ int8_t g_x8h[(size_t)T_DIM * OBS];
__device__ int8_t g_x8l[(size_t)T_DIM * OBS];
__device__ int8_t g_w8h[4ull * HID * OBS];
__device__ int8_t g_w8l[4ull * HID * OBS];
__device__ float g_sx[T_DIM];
__device__ float g_sw[4 * HID];

// ---------------------------------------------------------------------------
__device__ __forceinline__ uint32_t smem_to_u32(const void* p) {
    uint32_t a;
    asm("{ .reg .u64 t; cvta.to.shared.u64 t, %1; cvt.u32.u64 %0, t; }" : "=r"(a) : "l"(p));
    return a;
}
__device__ __forceinline__ void cp16(uint32_t dst, const void* src) {
    asm volatile("cp.async.cg.shared.global [%0], [%1], 16;" :: "r"(dst), "l"(src));
}
__device__ __forceinline__ void cp_commit() { asm volatile("cp.async.commit_group;"); }
__device__ __forceinline__ void ldsm4(uint32_t* r, uint32_t addr) {
    asm volatile("ldmatrix.sync.aligned.m8n8.x4.shared.b16 {%0,%1,%2,%3}, [%4];"
                 : "=r"(r[0]), "=r"(r[1]), "=r"(r[2]), "=r"(r[3]) : "r"(addr));
}
__device__ __forceinline__ void mma_s8(int* c, const uint32_t* a, uint32_t b0, uint32_t b1) {
    asm volatile(
        "mma.sync.aligned.m16n8k32.row.col.s32.s8.s8.s32 "
        "{%0,%1,%2,%3}, {%4,%5,%6,%7}, {%8,%9}, {%0,%1,%2,%3};"
        : "+r"(c[0]), "+r"(c[1]), "+r"(c[2]), "+r"(c[3])
        : "r"(a[0]), "r"(a[1]), "r"(a[2]), "r"(a[3]), "r"(b0), "r"(b1));
}

// ---------------------------------------------------------------------------
// Per-row absmax -> scale.  One warp per row of length OBS=512.
// ---------------------------------------------------------------------------
__global__ void rowmax_kernel(const float* __restrict__ src, float* __restrict__ scale) {
    int warp = threadIdx.x >> 5;
    int lane = threadIdx.x & 31;
    int row = blockIdx.x * 8 + warp;
    const float* r = src + (size_t)row * OBS;
    float m = 1e-20f;
#pragma unroll
    for (int j = 0; j < OBS / 32; j++) m = fmaxf(m, fabsf(r[lane + j * 32]));
#pragma unroll
    for (int off = 16; off > 0; off >>= 1)
        m = fmaxf(m, __shfl_xor_sync(0xFFFFFFFFu, m, off));
    if (lane == 0) scale[row] = m / 32000.f;
}

// ---------------------------------------------------------------------------
// Quantize to int16 = hi*256 + lo, stored as two int8 planes. 4 elems/thread.
// ---------------------------------------------------------------------------
__device__ __forceinline__ void quant4(const float* src, const float* scale,
                                       int8_t* dh, int8_t* dl, size_t i4) {
    int row = (int)(i4 >> 9);   // OBS = 512
    float inv = 1.f / scale[row];
    float4 v = *(const float4*)(src + i4);
    int q0 = __float2int_rn(v.x * inv), q1 = __float2int_rn(v.y * inv);
    int q2 = __float2int_rn(v.z * inv), q3 = __float2int_rn(v.w * inv);
    int h0 = (q0 + 128) >> 8, h1 = (q1 + 128) >> 8;
    int h2 = (q2 + 128) >> 8, h3 = (q3 + 128) >> 8;
    char4 hc = make_char4((char)h0, (char)h1, (char)h2, (char)h3);
    char4 lc = make_char4((char)(q0 - (h0 << 8)), (char)(q1 - (h1 << 8)),
                          (char)(q2 - (h2 << 8)), (char)(q3 - (h3 << 8)));
    *(char4*)(dh + i4) = hc;
    *(char4*)(dl + i4) = lc;
}
__global__ void quant_x_kernel(const float* __restrict__ x) {
    size_t i4 = ((size_t)blockIdx.x * blockDim.x + threadIdx.x) * 4;
    quant4(x, g_sx, g_x8h, g_x8l, i4);
}
__global__ void quant_w_kernel(const float* __restrict__ w0, const float* __restrict__ w1,
                               const float* __restrict__ w2, const float* __restrict__ w3) {
    int z = blockIdx.y;
    const float* __restrict__ W = (z == 0) ? w0 : (z == 1) ? w1 : (z == 2) ? w2 : w3;
    size_t i4 = ((size_t)blockIdx.x * blockDim.x + threadIdx.x) * 4;
    size_t o = (size_t)z * HID * OBS;
    quant4(W, g_sw + z * HID, g_w8h + o, g_w8l + o, i4);
}

// ---------------------------------------------------------------------------
// IMMA GEMM: G[z][t][h] = X[t,:] . W_z[h,:] via int16-emulated int8 MMA.
// dot = (65536*A1 + 256*A2) * sx[t] * sw[h],  A1 = xh.Wh,  A2 = xh.Wl + xl.Wh.
// Block 128(m) x 64(n), 4 warps 2x2 (warp tile 64x32), k-slab 64 int8.
// 128 threads, 2 CTAs/SM. Double-buffered cp.async. 80B padded rows.
// ---------------------------------------------------------------------------
#define GBM 128
#define GBN 64
#define GBK 64
#define NS (OBS / GBK)           // 8
#define ROWB 80
#define A_BYTES (GBM * ROWB)     // 10240
#define B_BYTES (GBN * ROWB)     // 5120
#define STAGE_BYTES (2 * A_BYTES + 2 * B_BYTES)   // 30720
#define GEMM_SMEM (2 * STAGE_BYTES)               // 61440

__global__ __launch_bounds__(128, 2)
void gemm_imma_kernel() {
    extern __shared__ char smem[];
    const uint32_t sbase = smem_to_u32(smem);
    const int tid = threadIdx.x;
    const int wid = tid >> 5;
    const int lane = tid & 31;
    const int wm = wid >> 1;         // 0..1 -> m offset *64
    const int wn = wid & 1;          // 0..1 -> n offset *32

    const int z = blockIdx.z;
    const int n0 = blockIdx.x * GBN;
    const int m0 = blockIdx.y * GBM;
    const int8_t* __restrict__ wh = g_w8h + (size_t)z * HID * OBS;
    const int8_t* __restrict__ wl = g_w8l + (size_t)z * HID * OBS;
    const float* __restrict__ sw = g_sw + z * HID;
    float* __restrict__ G = g_buf[z];

    int acc1[4][4][4], acc2[4][4][4];   // [mi][n8][frag]
#pragma unroll
    for (int i = 0; i < 4; i++)
#pragma unroll
        for (int j = 0; j < 4; j++)
#pragma unroll
            for (int k = 0; k < 4; k++) { acc1[i][j][k] = 0; acc2[i][j][k] = 0; }

    auto load_stage = [&](int s, int bi) {
        const int k0 = s * GBK;
        const uint32_t st = sbase + bi * STAGE_BYTES;
        // A: 128 rows x 64 int8 (4 x 16B chunks), hi + lo
#pragma unroll
        for (int i = 0; i < 4; i++) {
            int idx = tid + 128 * i;          // 0..511
            int row = idx >> 2, c = idx & 3;
            size_t gsrc = (size_t)(m0 + row) * OBS + k0 + c * 16;
            uint32_t dst = st + row * ROWB + c * 16;
            cp16(dst,           g_x8h + gsrc);
            cp16(dst + A_BYTES, g_x8l + gsrc);
        }
        // B: 64 rows x 64 int8, hi + lo
#pragma unroll
        for (int i = 0; i < 2; i++) {
            int idx = tid + 128 * i;          // 0..255
            int row = idx >> 2, c = idx & 3;
            size_t gsrc = (size_t)(n0 + row) * OBS + k0 + c * 16;
            uint32_t dst = st + 2 * A_BYTES + row * ROWB + c * 16;
            cp16(dst,           wh + gsrc);
            cp16(dst + B_BYTES, wl + gsrc);
        }
        cp_commit();
    };

    load_stage(0, 0);

    for (int s = 0; s < NS; s++) {
        if (s + 1 < NS) {
            load_stage(s + 1, (s + 1) & 1);
            asm volatile("cp.async.wait_group 1;" ::: "memory");
        } else {
            asm volatile("cp.async.wait_group 0;" ::: "memory");
        }
        __syncthreads();

        const uint32_t ab = sbase + (s & 1) * STAGE_BYTES;   // A hi
        const uint32_t bb = ab + 2 * A_BYTES;                // B hi

#pragma unroll
        for (int ks = 0; ks < 2; ks++) {   // two k32 steps inside the 64B slab
            uint32_t xh[4][4], xl[4][4];
#pragma unroll
            for (int mi = 0; mi < 4; mi++) {
                uint32_t addr = ab + (wm * 64 + mi * 16 + (lane & 15)) * ROWB
                              + ks * 32 + (lane >> 4) * 16;
                ldsm4(xh[mi], addr);
                ldsm4(xl[mi], addr + A_BYTES);
            }
            uint32_t bh[2][4], bl[2][4];
#pragma unroll
            for (int np = 0; np < 2; np++) {
                uint32_t addr = bb + (wn * 32 + np * 16 + (lane >> 4) * 8 + (lane & 7)) * ROWB
                              + ks * 32 + ((lane >> 3) & 1) * 16;
                ldsm4(bh[np], addr);
                ldsm4(bl[np], addr + B_BYTES);
            }
            // sweep 1: A1 += xh . Wh
#pragma unroll
            for (int mi = 0; mi < 4; mi++)
#pragma unroll
                for (int np = 0; np < 2; np++) {
                    mma_s8(acc1[mi][np * 2],     xh[mi], bh[np][0], bh[np][1]);
                    mma_s8(acc1[mi][np * 2 + 1], xh[mi], bh[np][2], bh[np][3]);
                }
            // sweep 2: A2 += xh . Wl
#pragma unroll
            for (int mi = 0; mi < 4; mi++)
#pragma unroll
                for (int np = 0; np < 2; np++) {
                    mma_s8(acc2[mi][np * 2],     xh[mi], bl[np][0], bl[np][1]);
                    mma_s8(acc2[mi][np * 2 + 1], xh[mi], bl[np][2], bl[np][3]);
                }
            // sweep 3: A2 += xl . Wh
#pragma unroll
            for (int mi = 0; mi < 4; mi++)
#pragma unroll
                for (int np = 0; np < 2; np++) {
                    mma_s8(acc2[mi][np * 2],     xl[mi], bh[np][0], bh[np][1]);
                    mma_s8(acc2[mi][np * 2 + 1], xl[mi], bh[np][2], bh[np][3]);
                }
        }
        __syncthreads();
    }

    // Epilogue: dequantize and store.
#pragma unroll
    for (int mi = 0; mi < 4; mi++) {
        int row = m0 + wm * 64 + mi * 16 + (lane >> 2);
        float sx0 = g_sx[row], sx1 = g_sx[row + 8];
#pragma unroll
        for (int ni = 0; ni < 4; ni++) {
            int col = n0 + wn * 32 + ni * 8 + (lane & 3) * 2;
            float sw0 = sw[col], sw1 = sw[col + 1];
            float v0 = (65536.f * (float)acc1[mi][ni][0] + 256.f * (float)acc2[mi][ni][0]) * (sx0 * sw0);
            float v1 = (65536.f * (float)acc1[mi][ni][1] + 256.f * (float)acc2[mi][ni][1]) * (sx0 * sw1);
            float v2 = (65536.f * (float)acc1[mi][ni][2] + 256.f * (float)acc2[mi][ni][2]) * (sx1 * sw0);
            float v3 = (65536.f * (float)acc1[mi][ni][3] + 256.f * (float)acc2[mi][ni][3]) * (sx1 * sw1);
            *(float2*)(G + (size_t)row * HID + col)       = make_float2(v0, v1);
            *(float2*)(G + (size_t)(row + 8) * HID + col) = make_float2(v2, v3);
        }
    }
}

// ---------------------------------------------------------------------------
// Scan pass 1 (fused gating): a = exp(sigmoid(dr) * (-exp(A_log[h]))); bx = B*x_state
// ---------------------------------------------------------------------------
__global__ void scan_chunk_kernel(const float* __restrict__ A_log) {
    int h = blockIdx.x * blockDim.x + threadIdx.x;
    int c = blockIdx.y;
    float A = -expf(A_log[h]);
    size_t base = (size_t)(c * LC) * HID + h;
    float ap = 1.f, bb = 0.f;
#pragma unroll 4
    for (int i = 0; i < LC; i++) {
        float xs = g_buf[0][base];
        float Bv = g_buf[1][base];
        float dr = g_buf[3][base];
        float delta = 1.f / (1.f + __expf(-dr));
        float a = expf(delta * A);
        float bx = Bv * xs;
        g_buf[3][base] = a;
        g_buf[1][base] = bx;
        ap *= a;
        bb = a * bb + bx;
        base += HID;
    }
    g_aggA[c * HID + h] = ap;
    g_aggB[c * HID + h] = bb;
}

// ---------------------------------------------------------------------------
// Scan pass 2: warp-parallel scan of NCHUNK aggregates per channel.
// ---------------------------------------------------------------------------
__global__ void scan_agg_kernel() {
    int warp = threadIdx.x >> 5;
    int lane = threadIdx.x & 31;
    int h = blockIdx.x * 8 + warp;

    float a_loc[4], b_loc[4];
    float ca = 1.f, cb = 0.f;
    int cbase = lane * 4;
#pragma unroll
    for (int j = 0; j < 4; j++) {
        float a = g_aggA[(cbase + j) * HID + h];
        float b = g_aggB[(cbase + j) * HID + h];
        a_loc[j] = a; b_loc[j] = b;
        cb = a * cb + b;
        ca *= a;
    }
    float ia = ca, ib = cb;
#pragma unroll
    for (int off = 1; off < 32; off <<= 1) {
        float pa = __shfl_up_sync(0xFFFFFFFFu, ia, off);
        float pb = __shfl_up_sync(0xFFFFFFFFu, ib, off);
        if (lane >= off) {
            ib = ia * pb + ib;
            ia = ia * pa;
        }
    }
    float eb = __shfl_up_sync(0xFFFFFFFFu, ib, 1);
    if (lane == 0) eb = 0.f;
    float hcur = eb;
#pragma unroll
    for (int j = 0; j < 4; j++) {
        g_hinit[(cbase + j) * HID + h] = hcur;
        hcur = a_loc[j] * hcur + b_loc[j];
    }
}

// ---------------------------------------------------------------------------
// Scan pass 3: apply within chunk, y = C * h  -> g_buf[0]
// ---------------------------------------------------------------------------
__global__ void scan_apply_kernel() {
    int h = blockIdx.x * blockDim.x + threadIdx.x;
    int c = blockIdx.y;
    size_t base = (size_t)(c * LC) * HID + h;
    float hs = g_hinit[c * HID + h];
#pragma unroll 4
    for (int i = 0; i < LC; i++) {
        float a = g_buf[3][base];
        float bx = g_buf[1][base];
        hs = a * hs + bx;
        g_buf[0][base] = g_buf[2][base] * hs;
        base += HID;
    }
}

// ---------------------------------------------------------------------------
// Output projection: warp per timestep.
// ---------------------------------------------------------------------------
__global__ void out_kernel(const float* __restrict__ x,
                           const float* __restrict__ W_out,
                           const float* __restrict__ b_out,
                           const float* __restrict__ W_skip,
                           float* __restrict__ out) {
    int warp = threadIdx.x >> 5;
    int lane = threadIdx.x & 31;
    int t = blockIdx.x * (blockDim.x >> 5) + warp;
    if (t >= T_DIM) return;

    float acc[NOBJ];
#pragma unroll
    for (int n = 0; n < NOBJ; n++) acc[n] = 0.f;

    const float* yrow = g_buf[0] + (size_t)t * HID;
    for (int h = lane; h < HID; h += 32) {
        float yv = yrow[h];
#pragma unroll
        for (int n = 0; n < NOBJ; n++) acc[n] += yv * W_out[n * HID + h];
    }
    const float* xrow = x + (size_t)t * OBS;
    for (int o = lane; o < OBS; o += 32) {
        float xv = xrow[o];
#pragma unroll
        for (int n = 0; n < NOBJ; n++) acc[n] += xv * W_skip[n * OBS + o];
    }
#pragma unroll
    for (int n = 0; n < NOBJ; n++) {
#pragma unroll
        for (int off = 16; off > 0; off >>= 1)
            acc[n] += __shfl_down_sync(0xFFFFFFFFu, acc[n], off);
    }
    if (lane == 0) {
#pragma unroll
        for (int n = 0; n < NOBJ; n++)
            out[(size_t)t * NOBJ + n] = acc[n] + b_out[n];
    }
}

// ---------------------------------------------------------------------------
extern "C" void kernel_launch(void* const* d_in, const int* in_sizes, int n_in,
                              void* d_out, int out_size) {
    const float* x       = (const float*)d_in[0];
    const float* W_in    = (const float*)d_in[1];
    const float* W_B     = (const float*)d_in[2];
    const float* W_C     = (const float*)d_in[3];
    const float* W_delta = (const float*)d_in[4];
    const float* A_log   = (const float*)d_in[5];
    const float* W_out   = (const float*)d_in[6];
    const float* b_out   = (const float*)d_in[7];
    const float* W_skip  = (const float*)d_in[8];
    float* out = (float*)d_out;

    cudaFuncSetAttribute(gemm_imma_kernel, cudaFuncAttributeMaxDynamicSharedMemorySize, GEMM_SMEM);

    // 0) per-row scales + int16->int8x2 quantization
    // NOTE: __device__ symbols must be resolved via cudaGetSymbolAddress — passing
    // the shadow symbol directly from host code was the R8 correctness bug.
    float* sx = nullptr;
    float* sw = nullptr;
    cudaGetSymbolAddress((void**)&sx, g_sx);
    cudaGetSymbolAddress((void**)&sw, g_sw);
    rowmax_kernel<<<T_DIM / 8, 256>>>(x, sx);
    rowmax_kernel<<<HID / 8, 256>>>(W_in,    sw);
    rowmax_kernel<<<HID / 8, 256>>>(W_B,     sw + HID);
    rowmax_kernel<<<HID / 8, 256>>>(W_C,     sw + 2 * HID);
    rowmax_kernel<<<HID / 8, 256>>>(W_delta, sw + 3 * HID);
    quant_x_kernel<<<(T_DIM * OBS) / 1024, 256>>>(x);
    quant_w_kernel<<<dim3((HID * OBS) / 1024, 4), 256>>>(W_in, W_B, W_C, W_delta);

    // 1) 4 GEMMs on int8 tensor cores -> g_buf[0..3]
    gemm_imma_kernel<<<dim3(HID / GBN, T_DIM / GBM, 4), 128, GEMM_SMEM>>>();

    // 2+3) fused gating + chunked scan
    scan_chunk_kernel<<<dim3(HID / 256, NCHUNK), 256>>>(A_log);
    scan_agg_kernel<<<HID / 8, 256>>>();
    scan_apply_kernel<<<dim3(HID / 256, NCHUNK), 256>>>();

    // 4) output projection
    out_kernel<<<T_DIM / 8, 256>>>(x, W_out, b_out, W_skip, out);
}

// round 10
// speedup vs baseline: 1.6108x; 1.6108x over previous
#include <cuda_runtime.h>
#include <cuda_bf16.h>
#include <math.h>
#include <stdint.h>

#define T_DIM 8192
#define OBS 512
#define HID 2048
#define NOBJ 8

#define NCHUNK 128
#define LC (T_DIM / NCHUNK)   // 64

// ---------------------------------------------------------------------------
// Scratch (device globals; no allocation allowed).
// g_buf[0]=bx, g_buf[1]=y, g_buf[2]=C, g_buf[3]=delta_raw
__device__ float g_buf[4][(size_t)T_DIM * HID];
__device__ float g_aggA[NCHUNK * HID];
__device__ float g_aggB[NCHUNK * HID];
__device__ float g_hinit[NCHUNK * HID];
// bf16 hi/lo split operands
__device__ __nv_bfloat16 g_xhi[(size_t)T_DIM * OBS];
__device__ __nv_bfloat16 g_xlo[(size_t)T_DIM * OBS];
__device__ __nv_bfloat16 g_whi[4ull * HID * OBS];
__device__ __nv_bfloat16 g_wlo[4ull * HID * OBS];

// ---------------------------------------------------------------------------
__device__ __forceinline__ uint32_t smem_to_u32(const void* p) {
    uint32_t a;
    asm("{ .reg .u64 t; cvta.to.shared.u64 t, %1; cvt.u32.u64 %0, t; }" : "=r"(a) : "l"(p));
    return a;
}
__device__ __forceinline__ void cp16(uint32_t dst, const void* src) {
    asm volatile("cp.async.cg.shared.global [%0], [%1], 16;" :: "r"(dst), "l"(src));
}
__device__ __forceinline__ void cp_commit() { asm volatile("cp.async.commit_group;"); }
__device__ __forceinline__ void ldsm4(uint32_t* r, uint32_t addr) {
    asm volatile("ldmatrix.sync.aligned.m8n8.x4.shared.b16 {%0,%1,%2,%3}, [%4];"
                 : "=r"(r[0]), "=r"(r[1]), "=r"(r[2]), "=r"(r[3]) : "r"(addr));
}
__device__ __forceinline__ void mma16816(float* c, const uint32_t* a, uint32_t b0, uint32_t b1) {
    asm volatile(
        "mma.sync.aligned.m16n8k16.row.col.f32.bf16.bf16.f32 "
        "{%0,%1,%2,%3}, {%4,%5,%6,%7}, {%8,%9}, {%0,%1,%2,%3};"
        : "+f"(c[0]), "+f"(c[1]), "+f"(c[2]), "+f"(c[3])
        : "r"(a[0]), "r"(a[1]), "r"(a[2]), "r"(a[3]), "r"(b0), "r"(b1));
}
__device__ __forceinline__ uint32_t pack_bf16x2(float a, float b) {
    __nv_bfloat162 p = __floats2bfloat162_rn(a, b);
    return *(uint32_t*)&p;
}

// ---------------------------------------------------------------------------
// fp32 -> bf16 hi/lo conversion (vectorized)
// ---------------------------------------------------------------------------
__global__ void convert_x_kernel(const float* __restrict__ x) {
    size_t i = ((size_t)blockIdx.x * blockDim.x + threadIdx.x) * 4;
    float4 v = *(const float4*)(x + i);
    __nv_bfloat16 h0 = __float2bfloat16(v.x), h1 = __float2bfloat16(v.y);
    __nv_bfloat16 h2 = __float2bfloat16(v.z), h3 = __float2bfloat16(v.w);
    uint2 hp;
    hp.x = pack_bf16x2(__bfloat162float(h0), __bfloat162float(h1));
    hp.y = pack_bf16x2(__bfloat162float(h2), __bfloat162float(h3));
    *(uint2*)(g_xhi + i) = hp;
    uint2 lp;
    lp.x = pack_bf16x2(v.x - __bfloat162float(h0), v.y - __bfloat162float(h1));
    lp.y = pack_bf16x2(v.z - __bfloat162float(h2), v.w - __bfloat162float(h3));
    *(uint2*)(g_xlo + i) = lp;
}
__global__ void convert_w_kernel(const float* __restrict__ w0, const float* __restrict__ w1,
                                 const float* __restrict__ w2, const float* __restrict__ w3) {
    int z = blockIdx.y;
    const float* __restrict__ W = (z == 0) ? w0 : (z == 1) ? w1 : (z == 2) ? w2 : w3;
    size_t i = ((size_t)blockIdx.x * blockDim.x + threadIdx.x) * 4;
    float4 v = *(const float4*)(W + i);
    size_t o = (size_t)z * HID * OBS + i;
    __nv_bfloat16 h0 = __float2bfloat16(v.x), h1 = __float2bfloat16(v.y);
    __nv_bfloat16 h2 = __float2bfloat16(v.z), h3 = __float2bfloat16(v.w);
    uint2 hp;
    hp.x = pack_bf16x2(__bfloat162float(h0), __bfloat162float(h1));
    hp.y = pack_bf16x2(__bfloat162float(h2), __bfloat162float(h3));
    *(uint2*)(g_whi + o) = hp;
    uint2 lp;
    lp.x = pack_bf16x2(v.x - __bfloat162float(h0), v.y - __bfloat162float(h1));
    lp.y = pack_bf16x2(v.z - __bfloat162float(h2), v.w - __bfloat162float(h3));
    *(uint2*)(g_wlo + o) = lp;
}

// ---------------------------------------------------------------------------
// Common GEMM geometry (bf16 3-term hi/lo split, 80B padded rows)
// ---------------------------------------------------------------------------
#define GBK 32
#define NS (OBS / GBK)           // 16
#define ROWB 80

// ============================ PAIR KERNEL ==================================
// Computes s = x@W_in^T and b = x@W_B^T for a 128x64 tile, writes bx = s*b.
// (R7 component; measured ~115us/GEMM — reused verbatim.)
#define PBM 128
#define PBN 64
#define PA_BYTES (PBM * ROWB)                 // 10240
#define PB_BYTES (PBN * ROWB)                 // 5120 (per weight-part)
#define PSTAGE (2 * PA_BYTES + 4 * PB_BYTES)  // 40960
#define PSMEM (2 * PSTAGE)                    // 81920

__global__ __launch_bounds__(128, 2)
void gemm_pair_kernel() {
    extern __shared__ char smem[];
    const uint32_t sbase = smem_to_u32(smem);
    const int tid = threadIdx.x;
    const int wid = tid >> 5;
    const int lane = tid & 31;
    const int wm = wid >> 1;         // 0..1 -> m offset *64
    const int wn = wid & 1;          // 0..1 -> n offset *32

    const int n0 = blockIdx.x * PBN;
    const int m0 = blockIdx.y * PBM;
    const __nv_bfloat16* __restrict__ w0hi = g_whi;                       // W_in
    const __nv_bfloat16* __restrict__ w0lo = g_wlo;
    const __nv_bfloat16* __restrict__ w1hi = g_whi + (size_t)HID * OBS;   // W_B
    const __nv_bfloat16* __restrict__ w1lo = g_wlo + (size_t)HID * OBS;

    float accS[4][4][4], accB[4][4][4];
#pragma unroll
    for (int i = 0; i < 4; i++)
#pragma unroll
        for (int j = 0; j < 4; j++)
#pragma unroll
            for (int k = 0; k < 4; k++) { accS[i][j][k] = 0.f; accB[i][j][k] = 0.f; }

    auto load_stage = [&](int s, int bi) {
        const int k0 = s * GBK;
        const uint32_t st = sbase + bi * PSTAGE;
#pragma unroll
        for (int i = 0; i < 4; i++) {
            int idx = tid + 128 * i;          // 0..511
            int row = idx >> 2, c = idx & 3;
            size_t gsrc = (size_t)(m0 + row) * OBS + k0 + c * 8;
            uint32_t dst = st + row * ROWB + c * 16;
            cp16(dst,            g_xhi + gsrc);
            cp16(dst + PA_BYTES, g_xlo + gsrc);
        }
#pragma unroll
        for (int i = 0; i < 2; i++) {
            int idx = tid + 128 * i;          // 0..255
            int row = idx >> 2, c = idx & 3;
            size_t gsrc = (size_t)(n0 + row) * OBS + k0 + c * 8;
            uint32_t dst = st + 2 * PA_BYTES + row * ROWB + c * 16;
            cp16(dst,                w0hi + gsrc);
            cp16(dst + PB_BYTES,     w0lo + gsrc);
            cp16(dst + 2 * PB_BYTES, w1hi + gsrc);
            cp16(dst + 3 * PB_BYTES, w1lo + gsrc);
        }
        cp_commit();
    };

    load_stage(0, 0);

    for (int s = 0; s < NS; s++) {
        if (s + 1 < NS) {
            load_stage(s + 1, (s + 1) & 1);
            asm volatile("cp.async.wait_group 1;" ::: "memory");
        } else {
            asm volatile("cp.async.wait_group 0;" ::: "memory");
        }
        __syncthreads();

        const uint32_t ab = sbase + (s & 1) * PSTAGE;
        const uint32_t bb = ab + 2 * PA_BYTES;

#pragma unroll
        for (int ks = 0; ks < 2; ks++) {
            uint32_t ahi[4][4], alo[4][4];
#pragma unroll
            for (int mi = 0; mi < 4; mi++) {
                uint32_t addr = ab + (wm * 64 + mi * 16 + (lane & 15)) * ROWB
                              + ks * 32 + (lane >> 4) * 16;
                ldsm4(ahi[mi], addr);
                ldsm4(alo[mi], addr + PA_BYTES);
            }
            uint32_t b0h[2][4], b0l[2][4], b1h[2][4], b1l[2][4];
#pragma unroll
            for (int np = 0; np < 2; np++) {
                uint32_t addr = bb + (wn * 32 + np * 16 + (lane >> 4) * 8 + (lane & 7)) * ROWB
                              + ks * 32 + ((lane >> 3) & 1) * 16;
                ldsm4(b0h[np], addr);
                ldsm4(b0l[np], addr + PB_BYTES);
                ldsm4(b1h[np], addr + 2 * PB_BYTES);
                ldsm4(b1l[np], addr + 3 * PB_BYTES);
            }
#pragma unroll
            for (int mi = 0; mi < 4; mi++)
#pragma unroll
                for (int np = 0; np < 2; np++) {
                    mma16816(accS[mi][np * 2],     ahi[mi], b0h[np][0], b0h[np][1]);
                    mma16816(accS[mi][np * 2 + 1], ahi[mi], b0h[np][2], b0h[np][3]);
                    mma16816(accB[mi][np * 2],     ahi[mi], b1h[np][0], b1h[np][1]);
                    mma16816(accB[mi][np * 2 + 1], ahi[mi], b1h[np][2], b1h[np][3]);
                }
#pragma unroll
            for (int mi = 0; mi < 4; mi++)
#pragma unroll
                for (int np = 0; np < 2; np++) {
                    mma16816(accS[mi][np * 2],     ahi[mi], b0l[np][0], b0l[np][1]);
                    mma16816(accS[mi][np * 2 + 1], ahi[mi], b0l[np][2], b0l[np][3]);
                    mma16816(accB[mi][np * 2],     ahi[mi], b1l[np][0], b1l[np][1]);
                    mma16816(accB[mi][np * 2 + 1], ahi[mi], b1l[np][2], b1l[np][3]);
                }
#pragma unroll
            for (int mi = 0; mi < 4; mi++)
#pragma unroll
                for (int np = 0; np < 2; np++) {
                    mma16816(accS[mi][np * 2],     alo[mi], b0h[np][0], b0h[np][1]);
                    mma16816(accS[mi][np * 2 + 1], alo[mi], b0h[np][2], b0h[np][3]);
                    mma16816(accB[mi][np * 2],     alo[mi], b1h[np][0], b1h[np][1]);
                    mma16816(accB[mi][np * 2 + 1], alo[mi], b1h[np][2], b1h[np][3]);
                }
        }
        __syncthreads();
    }

    // Epilogue: bx = s * b
    float* __restrict__ BX = g_buf[0];
#pragma unroll
    for (int mi = 0; mi < 4; mi++) {
        int row = m0 + wm * 64 + mi * 16 + (lane >> 2);
#pragma unroll
        for (int ni = 0; ni < 4; ni++) {
            int col = n0 + wn * 32 + ni * 8 + (lane & 3) * 2;
            *(float2*)(BX + (size_t)row * HID + col) =
                make_float2(accS[mi][ni][0] * accB[mi][ni][0],
                            accS[mi][ni][1] * accB[mi][ni][1]);
            *(float2*)(BX + (size_t)(row + 8) * HID + col) =
                make_float2(accS[mi][ni][2] * accB[mi][ni][2],
                            accS[mi][ni][3] * accB[mi][ni][3]);
        }
    }
}

// ============================ C / DELTA KERNEL =============================
// Plain R5 epilogue (no gating — avoids R7's register blowup).
// z=0: C -> g_buf[2].   z=1: delta_raw -> g_buf[3].
#define GBM 128
#define GBN 128
#define A_BYTES (GBM * ROWB)     // 10240
#define B_BYTES (GBN * ROWB)     // 10240
#define STAGE_BYTES (2 * A_BYTES + 2 * B_BYTES)   // 40960
#define GEMM_SMEM (2 * STAGE_BYTES)               // 81920

__global__ __launch_bounds__(128, 2)
void gemm_cd_kernel() {
    extern __shared__ char smem[];
    const uint32_t sbase = smem_to_u32(smem);
    const int tid = threadIdx.x;
    const int wid = tid >> 5;
    const int lane = tid & 31;
    const int wm = wid >> 1;
    const int wn = wid & 1;

    const int z = blockIdx.z;                 // 0 = C, 1 = delta
    const int n0 = blockIdx.x * GBN;
    const int m0 = blockIdx.y * GBM;
    const __nv_bfloat16* __restrict__ whi = g_whi + (size_t)(2 + z) * HID * OBS;
    const __nv_bfloat16* __restrict__ wlo = g_wlo + (size_t)(2 + z) * HID * OBS;
    float* __restrict__ G = g_buf[2 + z];

    float acc[4][8][4];
#pragma unroll
    for (int i = 0; i < 4; i++)
#pragma unroll
        for (int j = 0; j < 8; j++)
#pragma unroll
            for (int k = 0; k < 4; k++) acc[i][j][k] = 0.f;

    auto load_stage = [&](int s, int bi) {
        const int k0 = s * GBK;
        const uint32_t st = sbase + bi * STAGE_BYTES;
#pragma unroll
        for (int i = 0; i < 4; i++) {
            int idx = tid + 128 * i;
            int row = idx >> 2, c = idx & 3;
            size_t gsrc = (size_t)(m0 + row) * OBS + k0 + c * 8;
            uint32_t dst = st + row * ROWB + c * 16;
            cp16(dst,           g_xhi + gsrc);
            cp16(dst + A_BYTES, g_xlo + gsrc);
        }
#pragma unroll
        for (int i = 0; i < 4; i++) {
            int idx = tid + 128 * i;
            int row = idx >> 2, c = idx & 3;
            size_t gsrc = (size_t)(n0 + row) * OBS + k0 + c * 8;
            uint32_t dst = st + 2 * A_BYTES + row * ROWB + c * 16;
            cp16(dst,           whi + gsrc);
            cp16(dst + B_BYTES, wlo + gsrc);
        }
        cp_commit();
    };

    load_stage(0, 0);

    for (int s = 0; s < NS; s++) {
        if (s + 1 < NS) {
            load_stage(s + 1, (s + 1) & 1);
            asm volatile("cp.async.wait_group 1;" ::: "memory");
        } else {
            asm volatile("cp.async.wait_group 0;" ::: "memory");
        }
        __syncthreads();

        const uint32_t ab = sbase + (s & 1) * STAGE_BYTES;
        const uint32_t bb = ab + 2 * A_BYTES;

#pragma unroll
        for (int ks = 0; ks < 2; ks++) {
            uint32_t ahi[4][4], alo[4][4];
#pragma unroll
            for (int mi = 0; mi < 4; mi++) {
                uint32_t addr = ab + (wm * 64 + mi * 16 + (lane & 15)) * ROWB
                              + ks * 32 + (lane >> 4) * 16;
                ldsm4(ahi[mi], addr);
                ldsm4(alo[mi], addr + A_BYTES);
            }
            uint32_t bhi[4][4], blo[4][4];
#pragma unroll
            for (int np = 0; np < 4; np++) {
                uint32_t addr = bb + (wn * 64 + np * 16 + (lane >> 4) * 8 + (lane & 7)) * ROWB
                              + ks * 32 + ((lane >> 3) & 1) * 16;
                ldsm4(bhi[np], addr);
                ldsm4(blo[np], addr + B_BYTES);
            }
#pragma unroll
            for (int mi = 0; mi < 4; mi++)
#pragma unroll
                for (int np = 0; np < 4; np++) {
                    mma16816(acc[mi][np * 2],     ahi[mi], bhi[np][0], bhi[np][1]);
                    mma16816(acc[mi][np * 2 + 1], ahi[mi], bhi[np][2], bhi[np][3]);
                }
#pragma unroll
            for (int mi = 0; mi < 4; mi++)
#pragma unroll
                for (int np = 0; np < 4; np++) {
                    mma16816(acc[mi][np * 2],     ahi[mi], blo[np][0], blo[np][1]);
                    mma16816(acc[mi][np * 2 + 1], ahi[mi], blo[np][2], blo[np][3]);
                }
#pragma unroll
            for (int mi = 0; mi < 4; mi++)
#pragma unroll
                for (int np = 0; np < 4; np++) {
                    mma16816(acc[mi][np * 2],     alo[mi], bhi[np][0], bhi[np][1]);
                    mma16816(acc[mi][np * 2 + 1], alo[mi], bhi[np][2], bhi[np][3]);
                }
        }
        __syncthreads();
    }

#pragma unroll
    for (int mi = 0; mi < 4; mi++) {
        int row = m0 + wm * 64 + mi * 16 + (lane >> 2);
#pragma unroll
        for (int ni = 0; ni < 8; ni++) {
            int col = n0 + wn * 64 + ni * 8 + (lane & 3) * 2;
            *(float2*)(G + (size_t)row * HID + col) =
                make_float2(acc[mi][ni][0], acc[mi][ni][1]);
            *(float2*)(G + (size_t)(row + 8) * HID + col) =
                make_float2(acc[mi][ni][2], acc[mi][ni][3]);
        }
    }
}

// ---------------------------------------------------------------------------
// Scan pass 1: per-chunk aggregates. a recomputed from delta_raw; no stores.
// ---------------------------------------------------------------------------
__global__ void scan_chunk_kernel(const float* __restrict__ A_log) {
    int h = blockIdx.x * blockDim.x + threadIdx.x;
    int c = blockIdx.y;
    float A = -expf(A_log[h]);
    size_t base = (size_t)(c * LC) * HID + h;
    float ap = 1.f, bb = 0.f;
#pragma unroll 4
    for (int i = 0; i < LC; i++) {
        float dr = g_buf[3][base];
        float bx = g_buf[0][base];
        float a = expf(A / (1.f + __expf(-dr)));
        ap *= a;
        bb = a * bb + bx;
        base += HID;
    }
    g_aggA[c * HID + h] = ap;
    g_aggB[c * HID + h] = bb;
}

// ---------------------------------------------------------------------------
// Scan pass 2: warp-parallel scan of NCHUNK aggregates per channel.
// ---------------------------------------------------------------------------
__global__ void scan_agg_kernel() {
    int warp = threadIdx.x >> 5;
    int lane = threadIdx.x & 31;
    int h = blockIdx.x * 8 + warp;

    float a_loc[4], b_loc[4];
    float ca = 1.f, cb = 0.f;
    int cbase = lane * 4;
#pragma unroll
    for (int j = 0; j < 4; j++) {
        float a = g_aggA[(cbase + j) * HID + h];
        float b = g_aggB[(cbase + j) * HID + h];
        a_loc[j] = a; b_loc[j] = b;
        cb = a * cb + b;
        ca *= a;
    }
    float ia = ca, ib = cb;
#pragma unroll
    for (int off = 1; off < 32; off <<= 1) {
        float pa = __shfl_up_sync(0xFFFFFFFFu, ia, off);
        float pb = __shfl_up_sync(0xFFFFFFFFu, ib, off);
        if (lane >= off) {
            ib = ia * pb + ib;
            ia = ia * pa;
        }
    }
    float eb = __shfl_up_sync(0xFFFFFFFFu, ib, 1);
    if (lane == 0) eb = 0.f;
    float hcur = eb;
#pragma unroll
    for (int j = 0; j < 4; j++) {
        g_hinit[(cbase + j) * HID + h] = hcur;
        hcur = a_loc[j] * hcur + b_loc[j];
    }
}

// ---------------------------------------------------------------------------
// Scan pass 3: apply within chunk; a recomputed; y = C * h -> g_buf[1]
// ---------------------------------------------------------------------------
__global__ void scan_apply_kernel(const float* __restrict__ A_log) {
    int h = blockIdx.x * blockDim.x + threadIdx.x;
    int c = blockIdx.y;
    float A = -expf(A_log[h]);
    size_t base = (size_t)(c * LC) * HID + h;
    float hs = g_hinit[c * HID + h];
#pragma unroll 4
    for (int i = 0; i < LC; i++) {
        float dr = g_buf[3][base];
        float bx = g_buf[0][base];
        float a = expf(A / (1.f + __expf(-dr)));
        hs = a * hs + bx;
        g_buf[1][base] = g_buf[2][base] * hs;
        base += HID;
    }
}

// ---------------------------------------------------------------------------
// Output projection: warp per timestep.
// ---------------------------------------------------------------------------
__global__ void out_kernel(const float* __restrict__ x,
                           const float* __restrict__ W_out,
                           const float* __restrict__ b_out,
                           const float* __restrict__ W_skip,
                           float* __restrict__ out) {
    int warp = threadIdx.x >> 5;
    int lane = threadIdx.x & 31;
    int t = blockIdx.x * (blockDim.x >> 5) + warp;
    if (t >= T_DIM) return;

    float acc[NOBJ];
#pragma unroll
    for (int n = 0; n < NOBJ; n++) acc[n] = 0.f;

    const float* yrow = g_buf[1] + (size_t)t * HID;
    for (int h = lane; h < HID; h += 32) {
        float yv = yrow[h];
#pragma unroll
        for (int n = 0; n < NOBJ; n++) acc[n] += yv * W_out[n * HID + h];
    }
    const float* xrow = x + (size_t)t * OBS;
    for (int o = lane; o < OBS; o += 32) {
        float xv = xrow[o];
#pragma unroll
        for (int n = 0; n < NOBJ; n++) acc[n] += xv * W_skip[n * OBS + o];
    }
#pragma unroll
    for (int n = 0; n < NOBJ; n++) {
#pragma unroll
        for (int off = 16; off > 0; off >>= 1)
            acc[n] += __shfl_down_sync(0xFFFFFFFFu, acc[n], off);
    }
    if (lane == 0) {
#pragma unroll
        for (int n = 0; n < NOBJ; n++)
            out[(size_t)t * NOBJ + n] = acc[n] + b_out[n];
    }
}

// ---------------------------------------------------------------------------
extern "C" void kernel_launch(void* const* d_in, const int* in_sizes, int n_in,
                              void* d_out, int out_size) {
    const float* x       = (const float*)d_in[0];
    const float* W_in    = (const float*)d_in[1];
    const float* W_B     = (const float*)d_in[2];
    const float* W_C     = (const float*)d_in[3];
    const float* W_delta = (const float*)d_in[4];
    const float* A_log   = (const float*)d_in[5];
    const float* W_out   = (const float*)d_in[6];
    const float* b_out   = (const float*)d_in[7];
    const float* W_skip  = (const float*)d_in[8];
    float* out = (float*)d_out;

    cudaFuncSetAttribute(gemm_pair_kernel, cudaFuncAttributeMaxDynamicSharedMemorySize, PSMEM);
    cudaFuncSetAttribute(gemm_cd_kernel, cudaFuncAttributeMaxDynamicSharedMemorySize, GEMM_SMEM);

    // 0) bf16 hi/lo split of X and the four weight matrices
    convert_x_kernel<<<(T_DIM * OBS) / 1024, 256>>>(x);
    convert_w_kernel<<<dim3((HID * OBS) / 1024, 4), 256>>>(W_in, W_B, W_C, W_delta);

    // 1) GEMMs: pair (bx = x_state*B), then plain C and delta_raw
    gemm_pair_kernel<<<dim3(HID / PBN, T_DIM / PBM), 128, PSMEM>>>();
    gemm_cd_kernel<<<dim3(HID / GBN, T_DIM / GBM, 2), 128, GEMM_SMEM>>>();

    // 2+3) chunked scan; decay a recomputed from delta_raw in both passes
    scan_chunk_kernel<<<dim3(HID / 256, NCHUNK), 256>>>(A_log);
    scan_agg_kernel<<<HID / 8, 256>>>();
    scan_apply_kernel<<<dim3(HID / 256, NCHUNK), 256>>>(A_log);

    // 4) output projection
    out_kernel<<<T_DIM / 8, 256>>>(x, W_out, b_out, W_skip, out);
}

// round 11
// speedup vs baseline: 2.5296x; 1.5704x over previous
#include <cuda_runtime.h>
#include <cuda_bf16.h>
#include <cuda_fp16.h>
#include <math.h>
#include <stdint.h>

#define T_DIM 8192
#define OBS 512
#define HID 2048
#define NOBJ 8

#define NCHUNK 128
#define LC (T_DIM / NCHUNK)   // 64

// ---------------------------------------------------------------------------
// Scratch (device globals; no allocation allowed).
// g_h16[0]=x_state, g_h16[1]=B, g_h16[2]=C (fp16); g_buf[3]=delta_raw (fp32);
// g_buf[0]=y (fp32, scan output)
__device__ float g_buf[4][(size_t)T_DIM * HID];
__device__ __half g_h16[3][(size_t)T_DIM * HID];
__device__ float g_aggA[NCHUNK * HID];
__device__ float g_aggB[NCHUNK * HID];
__device__ float g_hinit[NCHUNK * HID];
// bf16 hi/lo split operands
__device__ __nv_bfloat16 g_xhi[(size_t)T_DIM * OBS];
__device__ __nv_bfloat16 g_xlo[(size_t)T_DIM * OBS];
__device__ __nv_bfloat16 g_whi[4ull * HID * OBS];
__device__ __nv_bfloat16 g_wlo[4ull * HID * OBS];

// ---------------------------------------------------------------------------
__device__ __forceinline__ uint32_t smem_to_u32(const void* p) {
    uint32_t a;
    asm("{ .reg .u64 t; cvta.to.shared.u64 t, %1; cvt.u32.u64 %0, t; }" : "=r"(a) : "l"(p));
    return a;
}
__device__ __forceinline__ void cp16(uint32_t dst, const void* src) {
    asm volatile("cp.async.cg.shared.global [%0], [%1], 16;" :: "r"(dst), "l"(src));
}
__device__ __forceinline__ void cp_commit() { asm volatile("cp.async.commit_group;"); }
__device__ __forceinline__ void ldsm4(uint32_t* r, uint32_t addr) {
    asm volatile("ldmatrix.sync.aligned.m8n8.x4.shared.b16 {%0,%1,%2,%3}, [%4];"
                 : "=r"(r[0]), "=r"(r[1]), "=r"(r[2]), "=r"(r[3]) : "r"(addr));
}
__device__ __forceinline__ void mma16816(float* c, const uint32_t* a, uint32_t b0, uint32_t b1) {
    asm volatile(
        "mma.sync.aligned.m16n8k16.row.col.f32.bf16.bf16.f32 "
        "{%0,%1,%2,%3}, {%4,%5,%6,%7}, {%8,%9}, {%0,%1,%2,%3};"
        : "+f"(c[0]), "+f"(c[1]), "+f"(c[2]), "+f"(c[3])
        : "r"(a[0]), "r"(a[1]), "r"(a[2]), "r"(a[3]), "r"(b0), "r"(b1));
}
__device__ __forceinline__ uint32_t pack_bf16x2(float a, float b) {
    __nv_bfloat162 p = __floats2bfloat162_rn(a, b);
    return *(uint32_t*)&p;
}

// ---------------------------------------------------------------------------
// fp32 -> bf16 hi/lo conversion (vectorized)
// ---------------------------------------------------------------------------
__global__ void convert_x_kernel(const float* __restrict__ x) {
    size_t i = ((size_t)blockIdx.x * blockDim.x + threadIdx.x) * 4;
    float4 v = *(const float4*)(x + i);
    __nv_bfloat16 h0 = __float2bfloat16(v.x), h1 = __float2bfloat16(v.y);
    __nv_bfloat16 h2 = __float2bfloat16(v.z), h3 = __float2bfloat16(v.w);
    uint2 hp;
    hp.x = pack_bf16x2(__bfloat162float(h0), __bfloat162float(h1));
    hp.y = pack_bf16x2(__bfloat162float(h2), __bfloat162float(h3));
    *(uint2*)(g_xhi + i) = hp;
    uint2 lp;
    lp.x = pack_bf16x2(v.x - __bfloat162float(h0), v.y - __bfloat162float(h1));
    lp.y = pack_bf16x2(v.z - __bfloat162float(h2), v.w - __bfloat162float(h3));
    *(uint2*)(g_xlo + i) = lp;
}
__global__ void convert_w_kernel(const float* __restrict__ w0, const float* __restrict__ w1,
                                 const float* __restrict__ w2, const float* __restrict__ w3) {
    int z = blockIdx.y;
    const float* __restrict__ W = (z == 0) ? w0 : (z == 1) ? w1 : (z == 2) ? w2 : w3;
    size_t i = ((size_t)blockIdx.x * blockDim.x + threadIdx.x) * 4;
    float4 v = *(const float4*)(W + i);
    size_t o = (size_t)z * HID * OBS + i;
    __nv_bfloat16 h0 = __float2bfloat16(v.x), h1 = __float2bfloat16(v.y);
    __nv_bfloat16 h2 = __float2bfloat16(v.z), h3 = __float2bfloat16(v.w);
    uint2 hp;
    hp.x = pack_bf16x2(__bfloat162float(h0), __bfloat162float(h1));
    hp.y = pack_bf16x2(__bfloat162float(h2), __bfloat162float(h3));
    *(uint2*)(g_whi + o) = hp;
    uint2 lp;
    lp.x = pack_bf16x2(v.x - __bfloat162float(h0), v.y - __bfloat162float(h1));
    lp.y = pack_bf16x2(v.z - __bfloat162float(h2), v.w - __bfloat162float(h3));
    *(uint2*)(g_wlo + o) = lp;
}

// ---------------------------------------------------------------------------
// HMMA GEMM (R5 monolithic, proven ~119us/GEMM): G[z] = X . W_z^T, bf16 3-term.
// BM=128, BN=128, BK=32. 4 warps 2x2, warp tile 64x64. 128 thr, 2 CTAs/SM.
// Epilogue: z<3 stores fp16 (x_state,B,C); z==3 stores fp32 delta_raw.
// ---------------------------------------------------------------------------
#define GBM 128
#define GBN 128
#define GBK 32
#define NS (OBS / GBK)           // 16
#define ROWB 80
#define A_BYTES (GBM * ROWB)     // 10240
#define B_BYTES (GBN * ROWB)     // 10240
#define STAGE_BYTES (2 * A_BYTES + 2 * B_BYTES)   // 40960
#define GEMM_SMEM (2 * STAGE_BYTES)               // 81920

__global__ __launch_bounds__(128, 2)
void gemm_hmma_kernel() {
    extern __shared__ char smem[];
    const uint32_t sbase = smem_to_u32(smem);
    const int tid = threadIdx.x;
    const int wid = tid >> 5;
    const int lane = tid & 31;
    const int wm = wid >> 1;         // 0..1 -> m offset *64
    const int wn = wid & 1;          // 0..1 -> n offset *64

    const int z = blockIdx.z;
    const int n0 = blockIdx.x * GBN;
    const int m0 = blockIdx.y * GBM;
    const __nv_bfloat16* __restrict__ whi = g_whi + (size_t)z * HID * OBS;
    const __nv_bfloat16* __restrict__ wlo = g_wlo + (size_t)z * HID * OBS;

    float acc[4][8][4];   // [mi][n8-frag][frag]
#pragma unroll
    for (int i = 0; i < 4; i++)
#pragma unroll
        for (int j = 0; j < 8; j++)
#pragma unroll
            for (int k = 0; k < 4; k++) acc[i][j][k] = 0.f;

    auto load_stage = [&](int s, int bi) {
        const int k0 = s * GBK;
        const uint32_t st = sbase + bi * STAGE_BYTES;
#pragma unroll
        for (int i = 0; i < 4; i++) {
            int idx = tid + 128 * i;          // 0..511
            int row = idx >> 2, c = idx & 3;
            size_t gsrc = (size_t)(m0 + row) * OBS + k0 + c * 8;
            uint32_t dst = st + row * ROWB + c * 16;
            cp16(dst,           g_xhi + gsrc);
            cp16(dst + A_BYTES, g_xlo + gsrc);
        }
#pragma unroll
        for (int i = 0; i < 4; i++) {
            int idx = tid + 128 * i;
            int row = idx >> 2, c = idx & 3;
            size_t gsrc = (size_t)(n0 + row) * OBS + k0 + c * 8;
            uint32_t dst = st + 2 * A_BYTES + row * ROWB + c * 16;
            cp16(dst,           whi + gsrc);
            cp16(dst + B_BYTES, wlo + gsrc);
        }
        cp_commit();
    };

    load_stage(0, 0);

    for (int s = 0; s < NS; s++) {
        if (s + 1 < NS) {
            load_stage(s + 1, (s + 1) & 1);
            asm volatile("cp.async.wait_group 1;" ::: "memory");
        } else {
            asm volatile("cp.async.wait_group 0;" ::: "memory");
        }
        __syncthreads();

        const uint32_t ab = sbase + (s & 1) * STAGE_BYTES;   // A hi
        const uint32_t bb = ab + 2 * A_BYTES;                // B hi

#pragma unroll
        for (int ks = 0; ks < 2; ks++) {
            uint32_t ahi[4][4], alo[4][4];
#pragma unroll
            for (int mi = 0; mi < 4; mi++) {
                uint32_t addr = ab + (wm * 64 + mi * 16 + (lane & 15)) * ROWB
                              + ks * 32 + (lane >> 4) * 16;
                ldsm4(ahi[mi], addr);
                ldsm4(alo[mi], addr + A_BYTES);
            }
            uint32_t bhi[4][4], blo[4][4];
#pragma unroll
            for (int np = 0; np < 4; np++) {
                uint32_t addr = bb + (wn * 64 + np * 16 + (lane >> 4) * 8 + (lane & 7)) * ROWB
                              + ks * 32 + ((lane >> 3) & 1) * 16;
                ldsm4(bhi[np], addr);
                ldsm4(blo[np], addr + B_BYTES);
            }
#pragma unroll
            for (int mi = 0; mi < 4; mi++)
#pragma unroll
                for (int np = 0; np < 4; np++) {
                    mma16816(acc[mi][np * 2],     ahi[mi], bhi[np][0], bhi[np][1]);
                    mma16816(acc[mi][np * 2 + 1], ahi[mi], bhi[np][2], bhi[np][3]);
                }
#pragma unroll
            for (int mi = 0; mi < 4; mi++)
#pragma unroll
                for (int np = 0; np < 4; np++) {
                    mma16816(acc[mi][np * 2],     ahi[mi], blo[np][0], blo[np][1]);
                    mma16816(acc[mi][np * 2 + 1], ahi[mi], blo[np][2], blo[np][3]);
                }
#pragma unroll
            for (int mi = 0; mi < 4; mi++)
#pragma unroll
                for (int np = 0; np < 4; np++) {
                    mma16816(acc[mi][np * 2],     alo[mi], bhi[np][0], bhi[np][1]);
                    mma16816(acc[mi][np * 2 + 1], alo[mi], bhi[np][2], bhi[np][3]);
                }
        }
        __syncthreads();
    }

    // Epilogue: z<3 -> fp16; z==3 (delta_raw) -> fp32
    if (z == 3) {
        float* __restrict__ G = g_buf[3];
#pragma unroll
        for (int mi = 0; mi < 4; mi++) {
            int row = m0 + wm * 64 + mi * 16 + (lane >> 2);
#pragma unroll
            for (int ni = 0; ni < 8; ni++) {
                int col = n0 + wn * 64 + ni * 8 + (lane & 3) * 2;
                *(float2*)(G + (size_t)row * HID + col) =
                    make_float2(acc[mi][ni][0], acc[mi][ni][1]);
                *(float2*)(G + (size_t)(row + 8) * HID + col) =
                    make_float2(acc[mi][ni][2], acc[mi][ni][3]);
            }
        }
    } else {
        __half* __restrict__ H = g_h16[z];
#pragma unroll
        for (int mi = 0; mi < 4; mi++) {
            int row = m0 + wm * 64 + mi * 16 + (lane >> 2);
#pragma unroll
            for (int ni = 0; ni < 8; ni++) {
                int col = n0 + wn * 64 + ni * 8 + (lane & 3) * 2;
                *(__half2*)(H + (size_t)row * HID + col) =
                    __floats2half2_rn(acc[mi][ni][0], acc[mi][ni][1]);
                *(__half2*)(H + (size_t)(row + 8) * HID + col) =
                    __floats2half2_rn(acc[mi][ni][2], acc[mi][ni][3]);
            }
        }
    }
}

// ---------------------------------------------------------------------------
// Scan pass 1: per-chunk aggregates only (no stores back).
// a and bx computed on the fly from fp16 xs/B and fp32 delta_raw.
// ---------------------------------------------------------------------------
__global__ void scan_chunk_kernel(const float* __restrict__ A_log) {
    int h = blockIdx.x * blockDim.x + threadIdx.x;
    int c = blockIdx.y;
    float A = -expf(A_log[h]);
    size_t base = (size_t)(c * LC) * HID + h;
    float ap = 1.f, bb = 0.f;
#pragma unroll 4
    for (int i = 0; i < LC; i++) {
        float dr = g_buf[3][base];
        float xs = __half2float(g_h16[0][base]);
        float Bv = __half2float(g_h16[1][base]);
        float delta = 1.f / (1.f + __expf(-dr));
        float a = expf(delta * A);
        float bx = Bv * xs;
        ap *= a;
        bb = a * bb + bx;
        base += HID;
    }
    g_aggA[c * HID + h] = ap;
    g_aggB[c * HID + h] = bb;
}

// ---------------------------------------------------------------------------
// Scan pass 2: warp-parallel scan of NCHUNK aggregates per channel.
// ---------------------------------------------------------------------------
__global__ void scan_agg_kernel() {
    int warp = threadIdx.x >> 5;
    int lane = threadIdx.x & 31;
    int h = blockIdx.x * 8 + warp;

    float a_loc[4], b_loc[4];
    float ca = 1.f, cb = 0.f;
    int cbase = lane * 4;
#pragma unroll
    for (int j = 0; j < 4; j++) {
        float a = g_aggA[(cbase + j) * HID + h];
        float b = g_aggB[(cbase + j) * HID + h];
        a_loc[j] = a; b_loc[j] = b;
        cb = a * cb + b;
        ca *= a;
    }
    float ia = ca, ib = cb;
#pragma unroll
    for (int off = 1; off < 32; off <<= 1) {
        float pa = __shfl_up_sync(0xFFFFFFFFu, ia, off);
        float pb = __shfl_up_sync(0xFFFFFFFFu, ib, off);
        if (lane >= off) {
            ib = ia * pb + ib;
            ia = ia * pa;
        }
    }
    float eb = __shfl_up_sync(0xFFFFFFFFu, ib, 1);
    if (lane == 0) eb = 0.f;
    float hcur = eb;
#pragma unroll
    for (int j = 0; j < 4; j++) {
        g_hinit[(cbase + j) * HID + h] = hcur;
        hcur = a_loc[j] * hcur + b_loc[j];
    }
}

// ---------------------------------------------------------------------------
// Scan pass 3: apply within chunk; recompute a, bx; y = C * h -> g_buf[0]
// ---------------------------------------------------------------------------
__global__ void scan_apply_kernel(const float* __restrict__ A_log) {
    int h = blockIdx.x * blockDim.x + threadIdx.x;
    int c = blockIdx.y;
    float A = -expf(A_log[h]);
    size_t base = (size_t)(c * LC) * HID + h;
    float hs = g_hinit[c * HID + h];
#pragma unroll 4
    for (int i = 0; i < LC; i++) {
        float dr = g_buf[3][base];
        float xs = __half2float(g_h16[0][base]);
        float Bv = __half2float(g_h16[1][base]);
        float Cv = __half2float(g_h16[2][base]);
        float delta = 1.f / (1.f + __expf(-dr));
        float a = expf(delta * A);
        hs = a * hs + Bv * xs;
        g_buf[0][base] = Cv * hs;
        base += HID;
    }
}

// ---------------------------------------------------------------------------
// Output projection: warp per timestep.
// ---------------------------------------------------------------------------
__global__ void out_kernel(const float* __restrict__ x,
                           const float* __restrict__ W_out,
                           const float* __restrict__ b_out,
                           const float* __restrict__ W_skip,
                           float* __restrict__ out) {
    int warp = threadIdx.x >> 5;
    int lane = threadIdx.x & 31;
    int t = blockIdx.x * (blockDim.x >> 5) + warp;
    if (t >= T_DIM) return;

    float acc[NOBJ];
#pragma unroll
    for (int n = 0; n < NOBJ; n++) acc[n] = 0.f;

    const float* yrow = g_buf[0] + (size_t)t * HID;
    for (int h = lane; h < HID; h += 32) {
        float yv = yrow[h];
#pragma unroll
        for (int n = 0; n < NOBJ; n++) acc[n] += yv * W_out[n * HID + h];
    }
    const float* xrow = x + (size_t)t * OBS;
    for (int o = lane; o < OBS; o += 32) {
        float xv = xrow[o];
#pragma unroll
        for (int n = 0; n < NOBJ; n++) acc[n] += xv * W_skip[n * OBS + o];
    }
#pragma unroll
    for (int n = 0; n < NOBJ; n++) {
#pragma unroll
        for (int off = 16; off > 0; off >>= 1)
            acc[n] += __shfl_down_sync(0xFFFFFFFFu, acc[n], off);
    }
    if (lane == 0) {
#pragma unroll
        for (int n = 0; n < NOBJ; n++)
            out[(size_t)t * NOBJ + n] = acc[n] + b_out[n];
    }
}

// ---------------------------------------------------------------------------
extern "C" void kernel_launch(void* const* d_in, const int* in_sizes, int n_in,
                              void* d_out, int out_size) {
    const float* x       = (const float*)d_in[0];
    const float* W_in    = (const float*)d_in[1];
    const float* W_B     = (const float*)d_in[2];
    const float* W_C     = (const float*)d_in[3];
    const float* W_delta = (const float*)d_in[4];
    const float* A_log   = (const float*)d_in[5];
    const float* W_out   = (const float*)d_in[6];
    const float* b_out   = (const float*)d_in[7];
    const float* W_skip  = (const float*)d_in[8];
    float* out = (float*)d_out;

    cudaFuncSetAttribute(gemm_hmma_kernel, cudaFuncAttributeMaxDynamicSharedMemorySize, GEMM_SMEM);

    // 0) bf16 hi/lo split of X and the four weight matrices
    convert_x_kernel<<<(T_DIM * OBS) / 1024, 256>>>(x);
    convert_w_kernel<<<dim3((HID * OBS) / 1024, 4), 256>>>(W_in, W_B, W_C, W_delta);

    // 1) 4 GEMMs on tensor cores; fp16 outputs for x_state/B/C, fp32 delta_raw
    gemm_hmma_kernel<<<dim3(HID / GBN, T_DIM / GBM, 4), 128, GEMM_SMEM>>>();

    // 2+3) chunked scan; a/bx recomputed from compact intermediates
    scan_chunk_kernel<<<dim3(HID / 256, NCHUNK), 256>>>(A_log);
    scan_agg_kernel<<<HID / 8, 256>>>();
    scan_apply_kernel<<<dim3(HID / 256, NCHUNK), 256>>>(A_log);

    // 4) output projection
    out_kernel<<<T_DIM / 8, 256>>>(x, W_out, b_out, W_skip, out);
}